// round 6
// baseline (speedup 1.0000x reference)
#include <cuda_runtime.h>

#define NN 192
#define CC 16
#define MM 16
#define K32 32
typedef unsigned long long u64;

__device__ __forceinline__ u64 fma2(u64 a, u64 b, u64 c) {
    u64 d; asm("fma.rn.f32x2 %0,%1,%2,%3;" : "=l"(d) : "l"(a), "l"(b), "l"(c)); return d;
}
__device__ __forceinline__ float2 up2(u64 v) {
    float2 r; asm("mov.b64 {%0,%1},%2;" : "=f"(r.x), "=f"(r.y) : "l"(v)); return r;
}
__device__ __forceinline__ u64 pk2(float a, float b) {
    u64 v; asm("mov.b64 %0,{%1,%2};" : "=l"(v) : "f"(a), "f"(b)); return v;
}

// ---------------- scratch (device globals; no runtime allocation) ----------------
static __device__ float2 g_A [(size_t)CC*NN*MM*NN];   // [c][x][kz][y]
static __device__ float2 g_B [(size_t)CC*K32*MM*NN];  // [c][kyl][kz][x]
static __device__ float2 g_Xf[(size_t)K32*K32*MM*CC]; // [kxl][kyl][kz][c]
static __device__ float2 g_Yf[(size_t)CC*K32*MM*K32]; // [o][kyl][kz][kxl]
static __device__ float2 g_G1[(size_t)CC*NN*MM*K32];  // [o][x][kz][kyl]
static __device__ float2 g_G2[(size_t)CC*NN*MM*NN];   // [o][x][kz][y]
static __device__ float2 g_Tzf[NN*MM];   // fwd z twiddle: (cos, -sin)
static __device__ float2 g_Tzi[NN*MM];   // inv z (hermitian weighted): (w cos, w sin)
static __device__ float2 g_Fnf[NN*K32];  // fwd x/y twiddle, n-major: (cos, -sin)
static __device__ float2 g_Fki[K32*NN];  // inv x/y twiddle, k-major: (cos, +sin)

// ---------------- twiddle tables (exact integer angle reduction, double sincos) ----
__global__ void k_tables() {
    int t = threadIdx.x;
    const double TWO_PI = 6.283185307179586476925286766559;
    for (int i = t; i < NN*MM; i += 256) {
        int z = i >> 4, kz = i & 15;
        double ang = TWO_PI * (double)((z * kz) % NN) / (double)NN;
        double s, c; sincos(ang, &s, &c);
        g_Tzf[i] = make_float2((float)c, (float)(-s));
        double w = (kz == 0) ? 1.0 : 2.0;
        g_Tzi[i] = make_float2((float)(w * c), (float)(w * s));
    }
    for (int i = t; i < NN*K32; i += 256) {
        int n = i >> 5, k = i & 31;
        int K = (k < MM) ? k : (k + 160);       // {0..15, 176..191}
        double ang = TWO_PI * (double)((n * K) % NN) / (double)NN;
        double s, c; sincos(ang, &s, &c);
        g_Fnf[n*K32 + k] = make_float2((float)c, (float)(-s));
        g_Fki[k*NN + n]  = make_float2((float)c, (float)(s));
    }
}

// ---------------- stage 1: forward DFT along z (real -> 16 complex) ----------------
// radix-2 fold: X[kz] = sum_{z<96} (x[z] +/- x[z+96]) * w(z,kz), sign by kz parity.
// block = 64 rows (one third of one (c,x)); 128 threads = 16 kz x 8 row-octets.
// smem holds fold planes TRANSPOSED [z][row] so row-pairs load as packed b64.
__global__ __launch_bounds__(128) void k_fz(const float* __restrict__ x) {
    extern __shared__ float sm[];
    float*  xsE = sm;                        // [96][66]
    float*  xsO = sm + 96*66;                // [96][66]
    float4* t4  = (float4*)(sm + 2*96*66);   // [96][16]: (c,c,-s,-s)
    const int tid = threadIdx.x;
    const size_t rbase = (size_t)blockIdx.x * 64;
    const float* src = x + rbase * NN;
    for (int i = tid; i < 64*96; i += 128) {
        int r = i / 96, z = i - r*96;
        float a = src[r*NN + z];
        float b = src[r*NN + z + 96];
        xsE[z*66 + r] = a + b;
        xsO[z*66 + r] = a - b;
    }
    for (int i = tid; i < 96*MM; i += 128) {
        float2 w = g_Tzf[i];
        t4[i] = make_float4(w.x, w.x, w.y, w.y);
    }
    __syncthreads();
    const int kz = tid & 15, rq = tid >> 4;
    const float* xs = (kz & 1) ? xsO : xsE;
    u64 ar0=0,ar1=0,ar2=0,ar3=0, ai0=0,ai1=0,ai2=0,ai3=0;
#pragma unroll 2
    for (int z = 0; z < 96; z++) {
        ulonglong2 t = *(const ulonglong2*)&t4[z*MM + kz];
        const u64* vp = (const u64*)(xs + z*66 + rq*8);
        u64 v0 = vp[0], v1 = vp[1], v2 = vp[2], v3 = vp[3];
        ar0 = fma2(v0, t.x, ar0); ai0 = fma2(v0, t.y, ai0);
        ar1 = fma2(v1, t.x, ar1); ai1 = fma2(v1, t.y, ai1);
        ar2 = fma2(v2, t.x, ar2); ai2 = fma2(v2, t.y, ai2);
        ar3 = fma2(v3, t.x, ar3); ai3 = fma2(v3, t.y, ai3);
    }
    const size_t cx = rbase / NN;
    const int y0 = (int)(rbase - cx*NN) + rq*8;
    float2* dst = g_A + (cx*MM + kz)*NN + y0;
    float2 r, i2;
    r = up2(ar0); i2 = up2(ai0); dst[0] = make_float2(r.x, i2.x); dst[1] = make_float2(r.y, i2.y);
    r = up2(ar1); i2 = up2(ai1); dst[2] = make_float2(r.x, i2.x); dst[3] = make_float2(r.y, i2.y);
    r = up2(ar2); i2 = up2(ai2); dst[4] = make_float2(r.x, i2.x); dst[5] = make_float2(r.y, i2.y);
    r = up2(ar3); i2 = up2(ai3); dst[6] = make_float2(r.x, i2.x); dst[7] = make_float2(r.y, i2.y);
}

// ---------------- stage 2: forward DFT along y (fold + f32x2 horizontal) -----------
// block = 16 rows = one (c,x) (all 16 kz); 256 threads = 32 kyl x 8 row-pairs.
// complex MAC: acc += (ax,ay)*(wx,-wy) -> re = hsum; acc2 += (ax,ay)*(wy,wx) -> im.
__global__ __launch_bounds__(256) void k_fy() {
    extern __shared__ float2 smf2[];
    float2* aE = smf2;                        // [96][17]
    float2* aO = smf2 + 96*17;                // [96][17]
    float4* t4 = (float4*)(smf2 + 2*96*17);   // [96][32]: (wx,-wy,wy,wx)
    const int tid = threadIdx.x;
    const size_t rbase = (size_t)blockIdx.x * 16;
    const float2* src = g_A + rbase * NN;
    for (int i = tid; i < 16*96; i += 256) {
        int r = i / 96, y = i - r*96;
        float2 a = src[r*NN + y];
        float2 b = src[r*NN + y + 96];
        aE[y*17 + r] = make_float2(a.x + b.x, a.y + b.y);
        aO[y*17 + r] = make_float2(a.x - b.x, a.y - b.y);
    }
    for (int i = tid; i < 96*K32; i += 256) {
        int y = i >> 5, k = i & 31;
        float2 w = g_Fnf[y*K32 + k];
        t4[i] = make_float4(w.x, -w.y, w.y, w.x);
    }
    __syncthreads();
    const int kyl = tid & 31, rp = tid >> 5;
    const float2* pl = (kyl & 1) ? aO : aE;
    u64 R0=0, I0=0, R1=0, I1=0;
#pragma unroll 2
    for (int y = 0; y < 96; y++) {
        u64 a0 = *(const u64*)&pl[y*17 + 2*rp];
        u64 a1 = *(const u64*)&pl[y*17 + 2*rp + 1];
        ulonglong2 t = *(const ulonglong2*)&t4[y*K32 + kyl];
        R0 = fma2(a0, t.x, R0); I0 = fma2(a0, t.y, I0);
        R1 = fma2(a1, t.x, R1); I1 = fma2(a1, t.y, I1);
    }
    const int c  = (int)(blockIdx.x / NN);
    const int xx = (int)(blockIdx.x % NN);
    float2 r0 = up2(R0), i0 = up2(I0), r1 = up2(R1), i1 = up2(I1);
    int kz0 = 2*rp, kz1 = 2*rp + 1;
    g_B[(((size_t)c*K32 + kyl)*MM + kz0)*NN + xx] = make_float2(r0.x + r0.y, i0.x + i0.y);
    g_B[(((size_t)c*K32 + kyl)*MM + kz1)*NN + xx] = make_float2(r1.x + r1.y, i1.x + i1.y);
}

// ---------------- stage 3: forward DFT along x (192 complex -> 32 modes) -----------
__global__ __launch_bounds__(256) void k_fx() {
    extern __shared__ float2 sm2[];
    float2* as = sm2;
    float2* tw = sm2 + 8*193;
    const int tid = threadIdx.x;
    const size_t rbase = (size_t)blockIdx.x * 8;
    const float2* src = g_B + rbase * NN;
    for (int i = tid; i < 8*NN; i += 256) {
        int r = i / NN, xx = i - r*NN;
        as[r*193 + xx] = src[i];
    }
    for (int i = tid; i < NN*K32; i += 256) tw[i] = g_Fnf[i];
    __syncthreads();
    const int kxl = tid & 31, r = tid >> 5;
    float re = 0.f, im = 0.f;
    const float2* arow = as + r*193;
#pragma unroll 4
    for (int xx = 0; xx < NN; xx++) {
        float2 a = arow[xx];
        float2 w = tw[xx*K32 + kxl];
        re = fmaf(a.x, w.x, re); re = fmaf(-a.y, w.y, re);
        im = fmaf(a.x, w.y, im); im = fmaf(a.y, w.x, im);
    }
    const size_t row = rbase + r;
    const int kz = (int)(row & 15);
    const size_t t2 = row >> 4;
    const int kyl = (int)(t2 & 31), c = (int)(t2 >> 5);
    g_Xf[(((size_t)kxl*K32 + kyl)*MM + kz)*CC + c] = make_float2(re, im);
}

// ---------------- stage M: per-mode 16x16 complex channel mixing -------------------
__global__ __launch_bounds__(256) void k_mix(const float* __restrict__ wr,
                                             const float* __restrict__ wi) {
    __shared__ float2 xfs[256];
    const int tid = threadIdx.x;
    const int kxl = blockIdx.x >> 5, kyl = blockIdx.x & 31;
    const int b   = (kxl >= MM ? 1 : 0) + (kyl >= MM ? 2 : 0);
    const int kxm = kxl & 15, kym = kyl & 15;
    {
        float2 v = g_Xf[((size_t)(kxl*K32 + kyl))*256 + tid];
        int kz = tid >> 4, i = tid & 15;
        xfs[i*MM + kz] = v;
    }
    __syncthreads();
    const int o = tid >> 4, kz = tid & 15;
    float re = 0.f, im = 0.f;
    const size_t wb = ((((size_t)b*MM)*MM + o)*MM + kxm)*MM*MM + (size_t)kym*MM + kz;
#pragma unroll
    for (int i = 0; i < MM; i++) {
        float2 xf = xfs[i*MM + kz];
        size_t widx = wb + (size_t)i * (MM*MM*MM*MM);
        float a = wr[widx], c = wi[widx];
        re = fmaf(xf.x, a, re); re = fmaf(-xf.y, c, re);
        im = fmaf(xf.x, c, im); im = fmaf(xf.y, a, im);
    }
    const float s = 1.0f / 7077888.0f;  // 1/192^3
    g_Yf[(((size_t)o*K32 + kyl)*MM + kz)*K32 + kxl] = make_float2(re*s, im*s);
}

// ---------------- stage 4: inverse DFT along x (32 modes -> 192, output fold) ------
// thread = x in [0,96); even/odd-k partial sums give x and x+96 together.
__global__ __launch_bounds__(96) void k_ix() {
    __shared__ __align__(16) float2 ys[32*K32];
    const int tid = threadIdx.x;
    const size_t rbase = (size_t)blockIdx.x * 32;
    const float2* src = g_Yf + rbase * K32;
    for (int i = tid; i < 32*K32; i += 96) ys[i] = src[i];
    __syncthreads();
    float twx[K32], twy[K32];
#pragma unroll
    for (int k = 0; k < K32; k++) {
        float2 w = g_Fki[k*NN + tid];
        twx[k] = w.x; twy[k] = w.y;
    }
    for (int r = 0; r < 32; r++) {
        float arp=0.f, arm=0.f, aip=0.f, aiq=0.f;
        float brp=0.f, brm=0.f, bip=0.f, biq=0.f;
        const float2* yr = ys + r*K32;
#pragma unroll
        for (int k = 0; k < K32; k++) {
            float2 v = yr[k];
            if (k & 1) {
                brp = fmaf(v.x, twx[k], brp); brm = fmaf(v.y, twy[k], brm);
                bip = fmaf(v.x, twy[k], bip); biq = fmaf(v.y, twx[k], biq);
            } else {
                arp = fmaf(v.x, twx[k], arp); arm = fmaf(v.y, twy[k], arm);
                aip = fmaf(v.x, twy[k], aip); aiq = fmaf(v.y, twx[k], aiq);
            }
        }
        float reA = arp - arm, imA = aip + aiq;
        float reB = brp - brm, imB = bip + biq;
        const size_t row = rbase + r;
        const int kz  = (int)(row & 15);
        const int kyl = (int)((row >> 4) & 31);
        const int o   = (int)(row >> 9);
        g_G1[(((size_t)o*NN + tid)*MM + kz)*K32 + kyl]        = make_float2(reA + reB, imA + imB);
        g_G1[(((size_t)o*NN + tid + 96)*MM + kz)*K32 + kyl]   = make_float2(reA - reB, imA - imB);
    }
}

// ---------------- stage 5: inverse DFT along y (32 modes -> 192, output fold) ------
__global__ __launch_bounds__(96) void k_iy() {
    __shared__ __align__(16) float2 ys[32*K32];
    const int tid = threadIdx.x;     // y in [0,96)
    const size_t rbase = (size_t)blockIdx.x * 32;
    const float2* src = g_G1 + rbase * K32;
    for (int i = tid; i < 32*K32; i += 96) ys[i] = src[i];
    __syncthreads();
    float twx[K32], twy[K32];
#pragma unroll
    for (int k = 0; k < K32; k++) {
        float2 w = g_Fki[k*NN + tid];
        twx[k] = w.x; twy[k] = w.y;
    }
    for (int r = 0; r < 32; r++) {
        float arp=0.f, arm=0.f, aip=0.f, aiq=0.f;
        float brp=0.f, brm=0.f, bip=0.f, biq=0.f;
        const float2* yr = ys + r*K32;
#pragma unroll
        for (int k = 0; k < K32; k++) {
            float2 v = yr[k];
            if (k & 1) {
                brp = fmaf(v.x, twx[k], brp); brm = fmaf(v.y, twy[k], brm);
                bip = fmaf(v.x, twy[k], bip); biq = fmaf(v.y, twx[k], biq);
            } else {
                arp = fmaf(v.x, twx[k], arp); arm = fmaf(v.y, twy[k], arm);
                aip = fmaf(v.x, twy[k], aip); aiq = fmaf(v.y, twx[k], aiq);
            }
        }
        float reA = arp - arm, imA = aip + aiq;
        float reB = brp - brm, imB = bip + biq;
        const size_t row = rbase + r;
        g_G2[row*NN + tid]      = make_float2(reA + reB, imA + imB);
        g_G2[row*NN + tid + 96] = make_float2(reA - reB, imA - imB);
    }
}

// ---------------- stage 6: inverse real DFT along z (fold + f32x2 horizontal) ------
// thread = z in [0,96); 16 packed twiddles (tc,ts) live in registers; the
// even/odd-kz split yields out[z] and out[z+96] from one pass over kz.
__global__ __launch_bounds__(96) void k_iz(float* __restrict__ out) {
    __shared__ __align__(16) float2 sg[MM*NN];   // [kz][y]
    const int tid = threadIdx.x;
    const size_t bi = blockIdx.x;
    const float2* src = g_G2 + bi * (MM*NN);
    for (int i = tid; i < MM*NN; i += 96) sg[i] = src[i];
    u64 tw[MM];
#pragma unroll
    for (int kz = 0; kz < MM; kz++) {
        float2 v = g_Tzi[tid*MM + kz];
        tw[kz] = pk2(v.x, -v.y);     // (tc, ts)
    }
    __syncthreads();
    float* dst = out + bi * (size_t)(NN*NN);
    for (int yp = 0; yp < 96; yp++) {
        u64 e0=0, e1=0, o0=0, o1=0;
#pragma unroll
        for (int kz = 0; kz < MM; kz++) {
            ulonglong2 v = *(const ulonglong2*)&sg[kz*NN + 2*yp];
            if (kz & 1) { o0 = fma2(v.x, tw[kz], o0); o1 = fma2(v.y, tw[kz], o1); }
            else        { e0 = fma2(v.x, tw[kz], e0); e1 = fma2(v.y, tw[kz], e1); }
        }
        float2 E0 = up2(e0), E1 = up2(e1), O0 = up2(o0), O1 = up2(o1);
        float eA = E0.x + E0.y, oA = O0.x + O0.y;
        float eB = E1.x + E1.y, oB = O1.x + O1.y;
        const int y0 = 2*yp;
        dst[(size_t)y0*NN + tid]          = eA + oA;
        dst[(size_t)y0*NN + tid + 96]     = eA - oA;
        dst[(size_t)(y0+1)*NN + tid]      = eB + oB;
        dst[(size_t)(y0+1)*NN + tid + 96] = eB - oB;
    }
}

// ---------------- launch ------------------------------------------------------------
extern "C" void kernel_launch(void* const* d_in, const int* in_sizes, int n_in,
                              void* d_out, int out_size) {
    (void)in_sizes; (void)n_in; (void)out_size;
    const float* x  = (const float*)d_in[0];
    const float* wr = (const float*)d_in[1];
    const float* wi = (const float*)d_in[2];
    float* out = (float*)d_out;

    const int SM1 = (2*96*66)*4 + 96*MM*16;          // 75264 B
    const int SM2 = (2*96*17)*8 + 96*K32*16;         // 75264 B
    const int SM3 = (8*193 + NN*K32) * 8;            // 61504 B

    cudaFuncSetAttribute(k_fz, cudaFuncAttributeMaxDynamicSharedMemorySize, SM1);
    cudaFuncSetAttribute(k_fy, cudaFuncAttributeMaxDynamicSharedMemorySize, SM2);
    cudaFuncSetAttribute(k_fx, cudaFuncAttributeMaxDynamicSharedMemorySize, SM3);

    k_tables<<<1, 256>>>();
    k_fz <<<(CC*NN*NN)/64, 128, SM1>>>(x);        // 9216 blocks
    k_fy <<<(CC*NN*MM)/16, 256, SM2>>>();         // 3072 blocks
    k_fx <<<(CC*K32*MM)/8, 256, SM3>>>();         // 1024 blocks
    k_mix<<<K32*K32,       256>>>(wr, wi);        // 1024 blocks
    k_ix <<<(CC*K32*MM)/32, 96>>>();              // 256 blocks
    k_iy <<<(CC*NN*MM)/32,  96>>>();              // 1536 blocks
    k_iz <<<CC*NN,          96>>>(out);           // 3072 blocks
}

// round 11
// speedup vs baseline: 1.3536x; 1.3536x over previous
#include <cuda_runtime.h>

#define NN 192
#define CC 16
#define MM 16
#define K32 32
typedef unsigned long long u64;

__device__ __forceinline__ u64 fma2(u64 a, u64 b, u64 c) {
    u64 d; asm("fma.rn.f32x2 %0,%1,%2,%3;" : "=l"(d) : "l"(a), "l"(b), "l"(c)); return d;
}
__device__ __forceinline__ float2 up2(u64 v) {
    float2 r; asm("mov.b64 {%0,%1},%2;" : "=f"(r.x), "=f"(r.y) : "l"(v)); return r;
}
__device__ __forceinline__ u64 pk2(float a, float b) {
    u64 v; asm("mov.b64 %0,{%1,%2};" : "=l"(v) : "f"(a), "f"(b)); return v;
}

// ---------------- scratch (device globals; no runtime allocation) ----------------
static __device__ float2 g_A [(size_t)CC*NN*MM*NN];   // [c][x][kz][y]
static __device__ float2 g_B [(size_t)CC*K32*MM*NN];  // [c][kyl][kz][x]
static __device__ float2 g_Xf[(size_t)K32*K32*MM*CC]; // [kxl][kyl][kz][c]
static __device__ float2 g_Yf[(size_t)CC*K32*MM*K32]; // [o][kyl][kz][kxl]
static __device__ float2 g_G1[(size_t)CC*NN*MM*K32];  // [o][x][kz][kyl]
static __device__ float2 g_G2[(size_t)CC*NN*MM*NN];   // [o][x][kz][y]
static __device__ float2 g_Tzf[NN*MM];   // fwd z twiddle: (cos, -sin)
static __device__ float2 g_Tzi[NN*MM];   // inv z (hermitian weighted): (w cos, w sin)
static __device__ float2 g_Fnf[NN*K32];  // fwd x/y twiddle, n-major: (cos, -sin)
static __device__ float2 g_Fki[K32*NN];  // inv x/y twiddle, k-major: (cos, +sin)

// ---------------- twiddle tables (exact integer angle reduction, double sincos) ----
__global__ void k_tables() {
    int t = blockIdx.x * blockDim.x + threadIdx.x;
    int stride = gridDim.x * blockDim.x;
    const double TWO_PI = 6.283185307179586476925286766559;
    for (int i = t; i < NN*MM; i += stride) {
        int z = i >> 4, kz = i & 15;
        double ang = TWO_PI * (double)((z * kz) % NN) / (double)NN;
        double s, c; sincos(ang, &s, &c);
        g_Tzf[i] = make_float2((float)c, (float)(-s));
        double w = (kz == 0) ? 1.0 : 2.0;
        g_Tzi[i] = make_float2((float)(w * c), (float)(w * s));
    }
    for (int i = t; i < NN*K32; i += stride) {
        int n = i >> 5, k = i & 31;
        int K = (k < MM) ? k : (k + 160);       // {0..15, 176..191}
        double ang = TWO_PI * (double)((n * K) % NN) / (double)NN;
        double s, c; sincos(ang, &s, &c);
        g_Fnf[n*K32 + k] = make_float2((float)c, (float)(-s));
        g_Fki[k*NN + n]  = make_float2((float)c, (float)(s));
    }
}

// ---------------- stage 1: forward DFT along z (real -> 16 complex) ----------------
// kz-pair f32x2 packing: even kz uses E-fold, odd uses O-fold, so data packs as
// (vE,vO) and twiddles as (c_2k, c_2k+1) / (-s_2k, -s_2k+1) broadcast LDS.128.
// block = one (c,x); 96 threads, thread owns y = {2t, 2t+1}; all 16 kz in regs.
#define ZC 32
#define YST 33   // padded z-chunk stride (float2) per y row
__global__ __launch_bounds__(96) void k_fz(const float* __restrict__ x) {
    extern __shared__ float smraw[];
    float2* xs = (float2*)smraw;                     // [192][YST] (vE,vO)
    float4* tw = (float4*)(smraw + 2*NN*YST);        // [96][8] (c0,c1,-s0,-s1)
    const int tid = threadIdx.x;
    const size_t bi = blockIdx.x;                    // (c,x)
    const float* src = x + bi * (size_t)(NN*NN);     // [y][z]

    for (int i = tid; i < 96*8; i += 96) {
        int z = i >> 3, kp = i & 7;
        float2 wa = g_Tzf[z*MM + 2*kp];
        float2 wb = g_Tzf[z*MM + 2*kp + 1];
        tw[i] = make_float4(wa.x, wb.x, wa.y, wb.y);
    }

    u64 ar0[8], ai0[8], ar1[8], ai1[8];
#pragma unroll
    for (int kp = 0; kp < 8; kp++) { ar0[kp]=0; ai0[kp]=0; ar1[kp]=0; ai1[kp]=0; }

    const int y0 = 2*tid, y1 = 2*tid + 1;
    for (int zb = 0; zb < 96; zb += ZC) {
        __syncthreads();
        // stage folds: i -> (y, zz-pair); two 8B stores (always naturally aligned)
        for (int i = tid; i < NN*(ZC/2); i += 96) {
            int zp = i & 15, y = i >> 4;
            int z = zb + 2*zp;
            float a0 = src[(size_t)y*NN + z];
            float a1 = src[(size_t)y*NN + z + 1];
            float b0 = src[(size_t)y*NN + z + 96];
            float b1 = src[(size_t)y*NN + z + 97];
            xs[y*YST + 2*zp]     = make_float2(a0 + b0, a0 - b0);
            xs[y*YST + 2*zp + 1] = make_float2(a1 + b1, a1 - b1);
        }
        __syncthreads();
#pragma unroll 4
        for (int zz = 0; zz < ZC; zz++) {
            u64 d0 = *(const u64*)&xs[y0*YST + zz];
            u64 d1 = *(const u64*)&xs[y1*YST + zz];
            const ulonglong2* twz = (const ulonglong2*)&tw[(zb + zz)*8];
#pragma unroll
            for (int kp = 0; kp < 8; kp++) {
                ulonglong2 t = twz[kp];
                ar0[kp] = fma2(d0, t.x, ar0[kp]); ai0[kp] = fma2(d0, t.y, ai0[kp]);
                ar1[kp] = fma2(d1, t.x, ar1[kp]); ai1[kp] = fma2(d1, t.y, ai1[kp]);
            }
        }
    }
    float2* dst = g_A + bi * (size_t)(MM*NN);
#pragma unroll
    for (int kp = 0; kp < 8; kp++) {
        float2 r0 = up2(ar0[kp]), i0 = up2(ai0[kp]);
        float2 r1 = up2(ar1[kp]), i1 = up2(ai1[kp]);
        dst[(2*kp)*NN + y0]   = make_float2(r0.x, i0.x);
        dst[(2*kp+1)*NN + y0] = make_float2(r0.y, i0.y);
        dst[(2*kp)*NN + y1]   = make_float2(r1.x, i1.x);
        dst[(2*kp+1)*NN + y1] = make_float2(r1.y, i1.y);
    }
}

// ---------------- stage 2: forward DFT along y (fold + f32x2 horizontal) -----------
__global__ __launch_bounds__(256) void k_fy() {
    extern __shared__ float2 smf2[];
    float2* aE = smf2;                        // [96][17]
    float2* aO = smf2 + 96*17;                // [96][17]
    float4* t4 = (float4*)(smf2 + 2*96*17);   // [96][32]: (wx,-wy,wy,wx)
    const int tid = threadIdx.x;
    const size_t rbase = (size_t)blockIdx.x * 16;
    const float2* src = g_A + rbase * NN;
    for (int i = tid; i < 16*96; i += 256) {
        int r = i / 96, y = i - r*96;
        float2 a = src[r*NN + y];
        float2 b = src[r*NN + y + 96];
        aE[y*17 + r] = make_float2(a.x + b.x, a.y + b.y);
        aO[y*17 + r] = make_float2(a.x - b.x, a.y - b.y);
    }
    for (int i = tid; i < 96*K32; i += 256) {
        int y = i >> 5, k = i & 31;
        float2 w = g_Fnf[y*K32 + k];
        t4[i] = make_float4(w.x, -w.y, w.y, w.x);
    }
    __syncthreads();
    const int kyl = tid & 31, rp = tid >> 5;
    const float2* pl = (kyl & 1) ? aO : aE;
    u64 R0=0, I0=0, R1=0, I1=0;
#pragma unroll 2
    for (int y = 0; y < 96; y++) {
        u64 a0 = *(const u64*)&pl[y*17 + 2*rp];
        u64 a1 = *(const u64*)&pl[y*17 + 2*rp + 1];
        ulonglong2 t = *(const ulonglong2*)&t4[y*K32 + kyl];
        R0 = fma2(a0, t.x, R0); I0 = fma2(a0, t.y, I0);
        R1 = fma2(a1, t.x, R1); I1 = fma2(a1, t.y, I1);
    }
    const int c  = (int)(blockIdx.x / NN);
    const int xx = (int)(blockIdx.x % NN);
    float2 r0 = up2(R0), i0 = up2(I0), r1 = up2(R1), i1 = up2(I1);
    int kz0 = 2*rp, kz1 = 2*rp + 1;
    g_B[(((size_t)c*K32 + kyl)*MM + kz0)*NN + xx] = make_float2(r0.x + r0.y, i0.x + i0.y);
    g_B[(((size_t)c*K32 + kyl)*MM + kz1)*NN + xx] = make_float2(r1.x + r1.y, i1.x + i1.y);
}

// ---------------- stage 3: forward DFT along x (fold + f32x2 horizontal) -----------
// block = 16 rows = one (c,kyl) (all 16 kz); 256 threads = 32 kxl x 8 kz-pairs.
__global__ __launch_bounds__(256) void k_fx() {
    extern __shared__ float2 smf2[];
    float2* aE = smf2;                        // [96][17]
    float2* aO = smf2 + 96*17;                // [96][17]
    float4* t4 = (float4*)(smf2 + 2*96*17);   // [96][32]: (wx,-wy,wy,wx)
    const int tid = threadIdx.x;
    const size_t rbase = (size_t)blockIdx.x * 16;
    const float2* src = g_B + rbase * NN;
    for (int i = tid; i < 16*96; i += 256) {
        int r = i / 96, xx = i - r*96;
        float2 a = src[r*NN + xx];
        float2 b = src[r*NN + xx + 96];
        aE[xx*17 + r] = make_float2(a.x + b.x, a.y + b.y);
        aO[xx*17 + r] = make_float2(a.x - b.x, a.y - b.y);
    }
    for (int i = tid; i < 96*K32; i += 256) {
        int xx = i >> 5, k = i & 31;
        float2 w = g_Fnf[xx*K32 + k];
        t4[i] = make_float4(w.x, -w.y, w.y, w.x);
    }
    __syncthreads();
    const int kxl = tid & 31, rp = tid >> 5;
    const float2* pl = (kxl & 1) ? aO : aE;
    u64 R0=0, I0=0, R1=0, I1=0;
#pragma unroll 2
    for (int xx = 0; xx < 96; xx++) {
        u64 a0 = *(const u64*)&pl[xx*17 + 2*rp];
        u64 a1 = *(const u64*)&pl[xx*17 + 2*rp + 1];
        ulonglong2 t = *(const ulonglong2*)&t4[xx*K32 + kxl];
        R0 = fma2(a0, t.x, R0); I0 = fma2(a0, t.y, I0);
        R1 = fma2(a1, t.x, R1); I1 = fma2(a1, t.y, I1);
    }
    const int c   = (int)(blockIdx.x >> 5);
    const int kyl = (int)(blockIdx.x & 31);
    float2 r0 = up2(R0), i0 = up2(I0), r1 = up2(R1), i1 = up2(I1);
    int kz0 = 2*rp, kz1 = 2*rp + 1;
    g_Xf[(((size_t)kxl*K32 + kyl)*MM + kz0)*CC + c] = make_float2(r0.x + r0.y, i0.x + i0.y);
    g_Xf[(((size_t)kxl*K32 + kyl)*MM + kz1)*CC + c] = make_float2(r1.x + r1.y, i1.x + i1.y);
}

// ---------------- stage M: per-mode 16x16 complex channel mixing -------------------
__global__ __launch_bounds__(256) void k_mix(const float* __restrict__ wr,
                                             const float* __restrict__ wi) {
    __shared__ float2 xfs[256];
    const int tid = threadIdx.x;
    const int kxl = blockIdx.x >> 5, kyl = blockIdx.x & 31;
    const int b   = (kxl >= MM ? 1 : 0) + (kyl >= MM ? 2 : 0);
    const int kxm = kxl & 15, kym = kyl & 15;
    {
        float2 v = g_Xf[((size_t)(kxl*K32 + kyl))*256 + tid];
        int kz = tid >> 4, i = tid & 15;
        xfs[i*MM + kz] = v;
    }
    __syncthreads();
    const int o = tid >> 4, kz = tid & 15;
    float re = 0.f, im = 0.f;
    const size_t wb = ((((size_t)b*MM)*MM + o)*MM + kxm)*MM*MM + (size_t)kym*MM + kz;
#pragma unroll
    for (int i = 0; i < MM; i++) {
        float2 xf = xfs[i*MM + kz];
        size_t widx = wb + (size_t)i * (MM*MM*MM*MM);
        float a = wr[widx], c = wi[widx];
        re = fmaf(xf.x, a, re); re = fmaf(-xf.y, c, re);
        im = fmaf(xf.x, c, im); im = fmaf(xf.y, a, im);
    }
    const float s = 1.0f / 7077888.0f;  // 1/192^3
    g_Yf[(((size_t)o*K32 + kyl)*MM + kz)*K32 + kxl] = make_float2(re*s, im*s);
}

// ---------------- stage 4: inverse DFT along x (32 modes -> 192, output fold) ------
// SoA smem + k-pair f32x2: data = broadcast LDS.64 (re or im pair), twiddles packed
// per k-pair in 32 u64 REGISTERS. Even-k sums land in lane.x, odd-k in lane.y.
__global__ __launch_bounds__(96) void k_ix() {
    __shared__ float ysr[32*K32];
    __shared__ float ysi[32*K32];
    const int tid = threadIdx.x;     // x in [0,96)
    const size_t rbase = (size_t)blockIdx.x * 32;
    const float2* src = g_Yf + rbase * K32;
    for (int i = tid; i < 32*K32; i += 96) {
        float2 v = src[i];
        ysr[i] = v.x; ysi[i] = v.y;
    }
    u64 txp[16], typ[16];
#pragma unroll
    for (int j = 0; j < 16; j++) {
        float2 w0 = g_Fki[(2*j)*NN + tid];
        float2 w1 = g_Fki[(2*j+1)*NN + tid];
        txp[j] = pk2(w0.x, w1.x);
        typ[j] = pk2(w0.y, w1.y);
    }
    __syncthreads();
    for (int r = 0; r < 32; r++) {
        u64 Crr=0, Cri=0, Cir=0, Cii=0;
        const float* pr = ysr + r*K32;
        const float* pi = ysi + r*K32;
#pragma unroll
        for (int j = 0; j < 16; j++) {
            u64 dre = *(const u64*)&pr[2*j];
            u64 dim = *(const u64*)&pi[2*j];
            Crr = fma2(dre, txp[j], Crr);
            Cri = fma2(dre, typ[j], Cri);
            Cir = fma2(dim, txp[j], Cir);
            Cii = fma2(dim, typ[j], Cii);
        }
        float2 crr = up2(Crr), cri = up2(Cri), cir = up2(Cir), cii = up2(Cii);
        float reE = crr.x - cii.x, reO = crr.y - cii.y;
        float imE = cri.x + cir.x, imO = cri.y + cir.y;
        const size_t row = rbase + r;
        const int kz  = (int)(row & 15);
        const int kyl = (int)((row >> 4) & 31);
        const int o   = (int)(row >> 9);
        g_G1[(((size_t)o*NN + tid)*MM + kz)*K32 + kyl]      = make_float2(reE + reO, imE + imO);
        g_G1[(((size_t)o*NN + tid + 96)*MM + kz)*K32 + kyl] = make_float2(reE - reO, imE - imO);
    }
}

// ---------------- stage 5: inverse DFT along y (32 modes -> 192, output fold) ------
__global__ __launch_bounds__(96) void k_iy() {
    __shared__ float ysr[32*K32];
    __shared__ float ysi[32*K32];
    const int tid = threadIdx.x;     // y in [0,96)
    const size_t rbase = (size_t)blockIdx.x * 32;
    const float2* src = g_G1 + rbase * K32;
    for (int i = tid; i < 32*K32; i += 96) {
        float2 v = src[i];
        ysr[i] = v.x; ysi[i] = v.y;
    }
    u64 txp[16], typ[16];
#pragma unroll
    for (int j = 0; j < 16; j++) {
        float2 w0 = g_Fki[(2*j)*NN + tid];
        float2 w1 = g_Fki[(2*j+1)*NN + tid];
        txp[j] = pk2(w0.x, w1.x);
        typ[j] = pk2(w0.y, w1.y);
    }
    __syncthreads();
    for (int r = 0; r < 32; r++) {
        u64 Crr=0, Cri=0, Cir=0, Cii=0;
        const float* pr = ysr + r*K32;
        const float* pi = ysi + r*K32;
#pragma unroll
        for (int j = 0; j < 16; j++) {
            u64 dre = *(const u64*)&pr[2*j];
            u64 dim = *(const u64*)&pi[2*j];
            Crr = fma2(dre, txp[j], Crr);
            Cri = fma2(dre, typ[j], Cri);
            Cir = fma2(dim, txp[j], Cir);
            Cii = fma2(dim, typ[j], Cii);
        }
        float2 crr = up2(Crr), cri = up2(Cri), cir = up2(Cir), cii = up2(Cii);
        float reE = crr.x - cii.x, reO = crr.y - cii.y;
        float imE = cri.x + cir.x, imO = cri.y + cir.y;
        const size_t row = rbase + r;
        g_G2[row*NN + tid]      = make_float2(reE + reO, imE + imO);
        g_G2[row*NN + tid + 96] = make_float2(reE - reO, imE - imO);
    }
}

// ---------------- stage 6: inverse real DFT along z (fold + f32x2 horizontal) ------
__global__ __launch_bounds__(96) void k_iz(float* __restrict__ out) {
    __shared__ __align__(16) float2 sg[MM*NN];   // [kz][y]
    const int tid = threadIdx.x;
    const size_t bi = blockIdx.x;
    const float2* src = g_G2 + bi * (MM*NN);
    for (int i = tid; i < MM*NN; i += 96) sg[i] = src[i];
    u64 tw[MM];
#pragma unroll
    for (int kz = 0; kz < MM; kz++) {
        float2 v = g_Tzi[tid*MM + kz];
        tw[kz] = pk2(v.x, -v.y);     // (tc, ts)
    }
    __syncthreads();
    float* dst = out + bi * (size_t)(NN*NN);
    for (int yp = 0; yp < 96; yp++) {
        u64 e0=0, e1=0, o0=0, o1=0;
#pragma unroll
        for (int kz = 0; kz < MM; kz++) {
            ulonglong2 v = *(const ulonglong2*)&sg[kz*NN + 2*yp];
            if (kz & 1) { o0 = fma2(v.x, tw[kz], o0); o1 = fma2(v.y, tw[kz], o1); }
            else        { e0 = fma2(v.x, tw[kz], e0); e1 = fma2(v.y, tw[kz], e1); }
        }
        float2 E0 = up2(e0), E1 = up2(e1), O0 = up2(o0), O1 = up2(o1);
        float eA = E0.x + E0.y, oA = O0.x + O0.y;
        float eB = E1.x + E1.y, oB = O1.x + O1.y;
        const int y0 = 2*yp;
        dst[(size_t)y0*NN + tid]          = eA + oA;
        dst[(size_t)y0*NN + tid + 96]     = eA - oA;
        dst[(size_t)(y0+1)*NN + tid]      = eB + oB;
        dst[(size_t)(y0+1)*NN + tid + 96] = eB - oB;
    }
}

// ---------------- launch ------------------------------------------------------------
extern "C" void kernel_launch(void* const* d_in, const int* in_sizes, int n_in,
                              void* d_out, int out_size) {
    (void)in_sizes; (void)n_in; (void)out_size;
    const float* x  = (const float*)d_in[0];
    const float* wr = (const float*)d_in[1];
    const float* wi = (const float*)d_in[2];
    float* out = (float*)d_out;

    const int SM1 = NN*YST*8 + 96*8*16;              // 50688 + 12288 = 62976 B
    const int SM2 = (2*96*17)*8 + 96*K32*16;         // 75264 B

    cudaFuncSetAttribute(k_fz, cudaFuncAttributeMaxDynamicSharedMemorySize, SM1);
    cudaFuncSetAttribute(k_fy, cudaFuncAttributeMaxDynamicSharedMemorySize, SM2);
    cudaFuncSetAttribute(k_fx, cudaFuncAttributeMaxDynamicSharedMemorySize, SM2);

    k_tables<<<24, 256>>>();
    k_fz <<<CC*NN,          96, SM1>>>(x);        // 3072 blocks
    k_fy <<<(CC*NN*MM)/16, 256, SM2>>>();         // 3072 blocks
    k_fx <<<CC*K32,        256, SM2>>>();         // 512 blocks
    k_mix<<<K32*K32,       256>>>(wr, wi);        // 1024 blocks
    k_ix <<<(CC*K32*MM)/32, 96>>>();              // 256 blocks
    k_iy <<<(CC*NN*MM)/32,  96>>>();              // 1536 blocks
    k_iz <<<CC*NN,          96>>>(out);           // 3072 blocks
}